// round 8
// baseline (speedup 1.0000x reference)
#include <cuda_runtime.h>

typedef unsigned long long ull;

// film buffer: [b(4)][ch(256)][tc(1024)]
__device__ float g_film[4 * 256 * 1024];

// ---------------- packed f32x2 helpers (sm_103a FFMA2 path) ----------------
__device__ __forceinline__ ull pk2(float lo, float hi) {
    ull r; asm("mov.b64 %0, {%1, %2};" : "=l"(r) : "f"(lo), "f"(hi)); return r;
}
__device__ __forceinline__ void upk2(float& lo, float& hi, ull v) {
    asm("mov.b64 {%0, %1}, %2;" : "=f"(lo), "=f"(hi) : "l"(v));
}
__device__ __forceinline__ ull ffma2(ull a, ull b, ull c) {
    ull d; asm("fma.rn.f32x2 %0, %1, %2, %3;" : "=l"(d) : "l"(a), "l"(b), "l"(c)); return d;
}
__device__ __forceinline__ ull fmul2(ull a, ull b) {
    ull d; asm("mul.rn.f32x2 %0, %1, %2;" : "=l"(d) : "l"(a), "l"(b)); return d;
}

// scalar Cody-Waite 2pi reduction + fast sin (constants become FFMA immediates)
__device__ __forceinline__ float sin_cw(float a) {
    const float MAGIC = 12582912.0f;
    float k = fmaf(a, 0.15915494309189535f, MAGIC);
    k = k - MAGIC;
    float r = fmaf(k, -6.2831854820251465f, a);
    r = fmaf(k, 1.7484556e-7f, r);
    return __sinf(r);
}

// ===========================================================================
// Kernel 1: control-rate MLP. 128 blocks x 256 threads, 32 positions/block.
// ===========================================================================
__global__ __launch_bounds__(256) void mlp_kernel(
    const float* __restrict__ cein,
    const float* __restrict__ W0, const float* __restrict__ B0,
    const float* __restrict__ G0, const float* __restrict__ Be0,
    const float* __restrict__ W1, const float* __restrict__ B1,
    const float* __restrict__ G1, const float* __restrict__ Be1,
    const float* __restrict__ W2, const float* __restrict__ B2,
    const float* __restrict__ G2, const float* __restrict__ Be2,
    const float* __restrict__ W3, const float* __restrict__ B3)
{
    extern __shared__ float sm1[];
    float* wbuf  = sm1;              // up to 128*257 = 32896 floats
    float* actA  = sm1 + 32896;      // 128 rows x pitch 36
    float* actB  = actA + 4608;
    float* biasS = actB + 4608;      // 256
    float* lngS  = biasS + 256;      // 128
    float* lnbS  = lngS + 128;       // 128
    float* statS = lnbS + 128;       // 64

    const int tid = threadIdx.x;
    const int P0  = blockIdx.x * 32;
    const int b   = P0 >> 10;
    const int tc0 = P0 & 1023;

    for (int i = tid; i < 128 * 32; i += 256) {
        int c = i >> 5, p = i & 31;
        actA[c * 36 + p] = cein[(b * 128 + c) * 1024 + tc0 + p];
    }

    const float* Wl[3]  = {W0, W1, W2};
    const float* Bl[3]  = {B0, B1, B2};
    const float* Gl[3]  = {G0, G1, G2};
    const float* Bel[3] = {Be0, Be1, Be2};

    float* ain  = actA;
    float* aout = actB;

    const int o     = tid & 127;
    const int half  = tid >> 7;
    const int pbase = half * 16;
    const int wrp   = tid >> 5;
    const int lane  = tid & 31;

    for (int layer = 0; layer < 3; layer++) {
        __syncthreads();
        const float* W = Wl[layer];
        for (int i = tid; i < 128 * 32; i += 256) {
            int oo = i >> 5, c4 = (i & 31) << 2;
            float4 w = *(const float4*)(W + oo * 128 + c4);
            wbuf[(c4 + 0) * 129 + oo] = w.x;
            wbuf[(c4 + 1) * 129 + oo] = w.y;
            wbuf[(c4 + 2) * 129 + oo] = w.z;
            wbuf[(c4 + 3) * 129 + oo] = w.w;
        }
        if (tid < 128) {
            biasS[tid] = Bl[layer][tid];
            lngS[tid]  = Gl[layer][tid];
            lnbS[tid]  = Bel[layer][tid];
        }
        __syncthreads();

        float acc[16];
        float bo = biasS[o];
#pragma unroll
        for (int p = 0; p < 16; p++) acc[p] = bo;

        const float* arow = ain + pbase;
#pragma unroll 4
        for (int c = 0; c < 128; c++) {
            float w = wbuf[c * 129 + o];
            const float4* hr = (const float4*)(arow + c * 36);
            float4 h0 = hr[0], h1 = hr[1], h2 = hr[2], h3 = hr[3];
            acc[0]  = fmaf(w, h0.x, acc[0]);  acc[1]  = fmaf(w, h0.y, acc[1]);
            acc[2]  = fmaf(w, h0.z, acc[2]);  acc[3]  = fmaf(w, h0.w, acc[3]);
            acc[4]  = fmaf(w, h1.x, acc[4]);  acc[5]  = fmaf(w, h1.y, acc[5]);
            acc[6]  = fmaf(w, h1.z, acc[6]);  acc[7]  = fmaf(w, h1.w, acc[7]);
            acc[8]  = fmaf(w, h2.x, acc[8]);  acc[9]  = fmaf(w, h2.y, acc[9]);
            acc[10] = fmaf(w, h2.z, acc[10]); acc[11] = fmaf(w, h2.w, acc[11]);
            acc[12] = fmaf(w, h3.x, acc[12]); acc[13] = fmaf(w, h3.y, acc[13]);
            acc[14] = fmaf(w, h3.z, acc[14]); acc[15] = fmaf(w, h3.w, acc[15]);
        }

        float4* orow = (float4*)(aout + o * 36 + pbase);
        orow[0] = make_float4(acc[0],  acc[1],  acc[2],  acc[3]);
        orow[1] = make_float4(acc[4],  acc[5],  acc[6],  acc[7]);
        orow[2] = make_float4(acc[8],  acc[9],  acc[10], acc[11]);
        orow[3] = make_float4(acc[12], acc[13], acc[14], acc[15]);
        __syncthreads();

#pragma unroll
        for (int pp = 0; pp < 4; pp++) {
            int p = wrp * 4 + pp;
            float s = 0.f, s2 = 0.f;
#pragma unroll
            for (int k = 0; k < 4; k++) {
                float v = aout[(lane + k * 32) * 36 + p];
                s += v; s2 = fmaf(v, v, s2);
            }
#pragma unroll
            for (int off = 16; off > 0; off >>= 1) {
                s  += __shfl_xor_sync(0xffffffffu, s,  off);
                s2 += __shfl_xor_sync(0xffffffffu, s2, off);
            }
            if (lane == 0) {
                float mu  = s * (1.f / 128.f);
                float var = fmaf(s2, 1.f / 128.f, -mu * mu);
                statS[2 * p]     = mu;
                statS[2 * p + 1] = rsqrtf(var + 1e-5f);
            }
        }
        __syncthreads();

        float g = lngS[o], bb = lnbS[o];
#pragma unroll
        for (int p = 0; p < 16; p++) {
            float mu = statS[2 * (pbase + p)];
            float rs = statS[2 * (pbase + p) + 1];
            float v  = fmaf((acc[p] - mu) * rs, g, bb);
            acc[p] = fmaxf(v, 0.01f * v);
        }
        orow[0] = make_float4(acc[0],  acc[1],  acc[2],  acc[3]);
        orow[1] = make_float4(acc[4],  acc[5],  acc[6],  acc[7]);
        orow[2] = make_float4(acc[8],  acc[9],  acc[10], acc[11]);
        orow[3] = make_float4(acc[12], acc[13], acc[14], acc[15]);

        float* tsw = ain; ain = aout; aout = tsw;
    }

    __syncthreads();
    for (int i = tid; i < 256 * 32; i += 256) {
        int oo = i >> 5, c4 = (i & 31) << 2;
        float4 w = *(const float4*)(W3 + oo * 128 + c4);
        wbuf[(c4 + 0) * 257 + oo] = w.x;
        wbuf[(c4 + 1) * 257 + oo] = w.y;
        wbuf[(c4 + 2) * 257 + oo] = w.z;
        wbuf[(c4 + 3) * 257 + oo] = w.w;
    }
    __syncthreads();
    {
        float acc[32];
        float bo = B3[tid];
#pragma unroll
        for (int p = 0; p < 32; p++) acc[p] = bo;
#pragma unroll 2
        for (int c = 0; c < 128; c++) {
            float w = wbuf[c * 257 + tid];
            const float4* hr = (const float4*)(ain + c * 36);
#pragma unroll
            for (int q = 0; q < 8; q++) {
                float4 h = hr[q];
                acc[q * 4 + 0] = fmaf(w, h.x, acc[q * 4 + 0]);
                acc[q * 4 + 1] = fmaf(w, h.y, acc[q * 4 + 1]);
                acc[q * 4 + 2] = fmaf(w, h.z, acc[q * 4 + 2]);
                acc[q * 4 + 3] = fmaf(w, h.w, acc[q * 4 + 3]);
            }
        }
        float4* dst = (float4*)(g_film + (b * 256 + tid) * 1024 + tc0);
#pragma unroll
        for (int q = 0; q < 8; q++)
            dst[q] = make_float4(acc[q * 4], acc[q * 4 + 1], acc[q * 4 + 2], acc[q * 4 + 3]);
    }
}

// ===========================================================================
// Kernel 2: FiLM interp + per-channel 1->16->16->1 sine MLP + mixer + x4 up.
// 2 blocks/SM x 512 threads (32 warps/SM). Warp owns 4 channels; lane owns
// one packed sample-pair. Layer 1 packs over OUTPUT pairs (o,o+1) in
// outer-product form: no h0 array, natural (non-duplicated) weight pairs.
// Task = 64 consecutive samples of one batch element.
// ===========================================================================
__global__ __launch_bounds__(512, 2) void newt_kernel(
    const float* __restrict__ ex, const float* __restrict__ iscale,
    const float* __restrict__ w0g, const float* __restrict__ b0g,
    const float* __restrict__ w1g, const float* __restrict__ b1g,
    const float* __restrict__ w2g, const float* __restrict__ b2g,
    const float* __restrict__ mixwg, const float* __restrict__ mixbg,
    float* __restrict__ outp)
{
    extern __shared__ float sm2[];
    float* sw1   = sm2;                 // 16384: [c][j][o], o fastest (natural pairs)
    float* sw0b0 = sm2 + 16384;         // 4096: per (c,j): {w0,w0,b0,b0}
    float* sb1   = sm2 + 20480;         // 1024: natural order (pairs b1[2p],b1[2p+1])
    float* sw2   = sm2 + 21504;         // 1024: natural order (pairs)
    float* sb2   = sm2 + 22528;         // 64 scalar
    float* smx   = sm2 + 22592;         // 128 dup
    float* sis   = sm2 + 22720;         // 128 dup
    ull*   red   = (ull*)(sm2 + 22848); // 512 ull

    const int tid = threadIdx.x;

    // stage weights
    for (int i = tid; i < 16384; i += 512) {
        int c = i >> 8, r = i & 255, j = r >> 4, o = r & 15;
        sw1[i] = w1g[(c << 8) + (o << 4) + j];
    }
    for (int i = tid; i < 1024; i += 512) {
        float w = w0g[i], bz = b0g[i];
        sw0b0[4 * i + 0] = w;  sw0b0[4 * i + 1] = w;
        sw0b0[4 * i + 2] = bz; sw0b0[4 * i + 3] = bz;
        sb1[i] = b1g[i];
        sw2[i] = w2g[i];
    }
    if (tid < 64) {
        sb2[tid] = b2g[tid];
        float m = mixwg[tid];  smx[2 * tid] = m; smx[2 * tid + 1] = m;
        float s = iscale[tid]; sis[2 * tid] = s; sis[2 * tid + 1] = s;
    }
    __syncthreads();

    const int lane = tid & 31;
    const int wid  = tid >> 5;
    const int side = lane >> 4;
    float f0 = (2 * lane) * 0.015625f + 0.0078125f + 0.5f - (float)side;
    const ull fracp = pk2(f0, f0 + 0.015625f);
    const ull ZZ = pk2(0.f, 0.f);

    for (int task = blockIdx.x; task < 4096; task += gridDim.x) {
        const int b  = task >> 10;
        const int tt = task & 1023;
        const int t0 = tt << 6;
        int iA = tt - 1 + side; if (iA < 0) iA = 0;
        int iB = tt + side;     if (iB > 1023) iB = 1023;

        ull mixP = ZZ;
#pragma unroll 1
        for (int k = 0; k < 4; k++) {
            const int c = (wid << 2) + k;
            const float* fr = g_film + b * 262144 + c * 1024;

            float ga = __ldg(fr + iA), gb = __ldg(fr + iB);
            float ba = __ldg(fr + 65536 + iA), bb = __ldg(fr + 65536 + iB);
            float2 e2 = *(const float2*)(ex + (((b << 6) + c) << 16) + t0 + 2 * lane);

            ull giP = ffma2(fracp, pk2(gb - ga, gb - ga), pk2(ga, ga));
            ull biP = ffma2(fracp, pk2(bb - ba, bb - ba), pk2(ba, ba));
            ull xP  = fmul2(ffma2(giP, pk2(e2.x, e2.y), biP),
                            *(const ull*)(sis + 2 * c));

            // init accumulators from b1 pairs: acc[2p+s] for o-pair p, sample s
            ull acc[16];
            {
                const ull* b1p = (const ull*)(sb1 + (c << 4));
#pragma unroll
                for (int p = 0; p < 8; p++) { acc[2 * p] = b1p[p]; acc[2 * p + 1] = b1p[p]; }
            }

            // layer 0 + layer 1 fused, outer-product over j
            const ulonglong2* wbp = (const ulonglong2*)(sw0b0) + (c << 4);
            const float* w1c = sw1 + (c << 8);
#pragma unroll
            for (int j = 0; j < 16; j++) {
                ulonglong2 wb = wbp[j];                 // (w0 dup, b0 dup)
                ull arg = ffma2(xP, wb.x, wb.y);
                float a0, a1; upk2(a0, a1, arg);
                float s0 = sin_cw(a0), s1 = sin_cw(a1);
                ull hh0 = pk2(s0, s0), hh1 = pk2(s1, s1);
                const ulonglong2* wr = (const ulonglong2*)(w1c + (j << 4));
#pragma unroll
                for (int q = 0; q < 4; q++) {
                    ulonglong2 wv = wr[q];
                    acc[4 * q + 0] = ffma2(hh0, wv.x, acc[4 * q + 0]);
                    acc[4 * q + 1] = ffma2(hh1, wv.x, acc[4 * q + 1]);
                    acc[4 * q + 2] = ffma2(hh0, wv.y, acc[4 * q + 2]);
                    acc[4 * q + 3] = ffma2(hh1, wv.y, acc[4 * q + 3]);
                }
            }

            // layer 2: sin(acc) dot w2 (packed over o-pairs)
            const ull* w2p = (const ull*)(sw2 + (c << 4));
            ull y0a = ZZ, y1a = ZZ;
#pragma unroll
            for (int p = 0; p < 8; p++) {
                float u0, u1, v0, v1;
                upk2(u0, u1, acc[2 * p]);
                upk2(v0, v1, acc[2 * p + 1]);
                ull wp = w2p[p];
                y0a = ffma2(pk2(__sinf(u0), __sinf(u1)), wp, y0a);
                y1a = ffma2(pk2(__sinf(v0), __sinf(v1)), wp, y1a);
            }
            float b2c = sb2[c];
            float y0l, y0h, y1l, y1h;
            upk2(y0l, y0h, y0a); upk2(y1l, y1h, y1a);
            float sy0 = __sinf(y0l + y0h + b2c);
            float sy1 = __sinf(y1l + y1h + b2c);

            // deferred gamma_n / beta_n + final FiLM + mix
            float na = __ldg(fr + 131072 + iA), nb = __ldg(fr + 131072 + iB);
            float pa = __ldg(fr + 196608 + iA), pb = __ldg(fr + 196608 + iB);
            ull gnP = ffma2(fracp, pk2(nb - na, nb - na), pk2(na, na));
            ull bnP = ffma2(fracp, pk2(pb - pa, pb - pa), pk2(pa, pa));
            ull oP  = ffma2(gnP, pk2(sy0, sy1), bnP);
            mixP = ffma2(*(const ull*)(smx + 2 * c), oP, mixP);
        }

        red[(wid << 5) + lane] = mixP;
        __syncthreads();
        if (tid < 64) {
            const float* rf = (const float*)red;
            float s = __ldg(mixbg);
#pragma unroll
            for (int w = 0; w < 16; w++) s += rf[(w << 6) + tid];
            *(float4*)(outp + (b << 18) + ((t0 + tid) << 2)) = make_float4(s, s, s, s);
        }
        __syncthreads();
    }
}

// ===========================================================================
extern "C" void kernel_launch(void* const* d_in, const int* in_sizes, int n_in,
                              void* d_out, int out_size) {
    const float* ex    = (const float*)d_in[0];
    const float* ce    = (const float*)d_in[1];
    const float* w0    = (const float*)d_in[2];
    const float* b0    = (const float*)d_in[3];
    const float* g0    = (const float*)d_in[4];
    const float* be0   = (const float*)d_in[5];
    const float* w1    = (const float*)d_in[6];
    const float* b1    = (const float*)d_in[7];
    const float* g1    = (const float*)d_in[8];
    const float* be1   = (const float*)d_in[9];
    const float* w2    = (const float*)d_in[10];
    const float* b2    = (const float*)d_in[11];
    const float* g2    = (const float*)d_in[12];
    const float* be2   = (const float*)d_in[13];
    const float* w3    = (const float*)d_in[14];
    const float* b3    = (const float*)d_in[15];
    const float* iscl  = (const float*)d_in[16];
    const float* sfw0  = (const float*)d_in[17];
    const float* sfb0  = (const float*)d_in[18];
    const float* sfw1  = (const float*)d_in[19];
    const float* sfb1  = (const float*)d_in[20];
    const float* sfw2  = (const float*)d_in[21];
    const float* sfb2  = (const float*)d_in[22];
    const float* mixw  = (const float*)d_in[23];
    const float* mixb  = (const float*)d_in[24];
    float* out = (float*)d_out;

    const int SM1 = 42688 * 4;   // 170752 B
    const int SM2 = 23872 * 4;   // 95488 B  -> 2 blocks/SM
    cudaFuncSetAttribute(mlp_kernel,  cudaFuncAttributeMaxDynamicSharedMemorySize, SM1);
    cudaFuncSetAttribute(newt_kernel, cudaFuncAttributeMaxDynamicSharedMemorySize, SM2);

    int nsm = 148;
    cudaDeviceGetAttribute(&nsm, cudaDevAttrMultiProcessorCount, 0);
    if (nsm <= 0) nsm = 148;

    mlp_kernel<<<128, 256, SM1>>>(ce, w0, b0, g0, be0, w1, b1, g1, be1,
                                  w2, b2, g2, be2, w3, b3);
    newt_kernel<<<2 * nsm, 512, SM2>>>(ex, iscl, sfw0, sfb0, sfw1, sfb1,
                                       sfw2, sfb2, mixw, mixb, out);
}

// round 10
// speedup vs baseline: 1.0603x; 1.0603x over previous
#include <cuda_runtime.h>

typedef unsigned long long ull;

// film buffer: [b(4)][ch(256)][tc(1024)]
__device__ float g_film[4 * 256 * 1024];

// ---------------- packed f32x2 helpers (sm_103a FFMA2 path) ----------------
__device__ __forceinline__ ull pk2(float lo, float hi) {
    ull r; asm("mov.b64 %0, {%1, %2};" : "=l"(r) : "f"(lo), "f"(hi)); return r;
}
__device__ __forceinline__ void upk2(float& lo, float& hi, ull v) {
    asm("mov.b64 {%0, %1}, %2;" : "=f"(lo), "=f"(hi) : "l"(v));
}
__device__ __forceinline__ ull ffma2(ull a, ull b, ull c) {
    ull d; asm("fma.rn.f32x2 %0, %1, %2, %3;" : "=l"(d) : "l"(a), "l"(b), "l"(c)); return d;
}

// scalar Cody-Waite 2pi reduction + fast sin (constants become FFMA immediates)
__device__ __forceinline__ float sin_cw(float a) {
    const float MAGIC = 12582912.0f;
    float k = fmaf(a, 0.15915494309189535f, MAGIC);
    k = fmaf(k, 1.0f, -MAGIC);
    float r = fmaf(k, -6.2831854820251465f, a);
    r = fmaf(k, 1.7484556e-7f, r);
    return __sinf(r);
}

// ===========================================================================
// Kernel 1: control-rate MLP. 128 blocks x 256 threads, 32 positions/block.
// ===========================================================================
__global__ __launch_bounds__(256) void mlp_kernel(
    const float* __restrict__ cein,
    const float* __restrict__ W0, const float* __restrict__ B0,
    const float* __restrict__ G0, const float* __restrict__ Be0,
    const float* __restrict__ W1, const float* __restrict__ B1,
    const float* __restrict__ G1, const float* __restrict__ Be1,
    const float* __restrict__ W2, const float* __restrict__ B2,
    const float* __restrict__ G2, const float* __restrict__ Be2,
    const float* __restrict__ W3, const float* __restrict__ B3)
{
    extern __shared__ float sm1[];
    float* wbuf  = sm1;              // up to 128*257 = 32896 floats
    float* actA  = sm1 + 32896;      // 128 rows x pitch 36
    float* actB  = actA + 4608;
    float* biasS = actB + 4608;      // 256
    float* lngS  = biasS + 256;      // 128
    float* lnbS  = lngS + 128;       // 128
    float* statS = lnbS + 128;       // 64

    const int tid = threadIdx.x;
    const int P0  = blockIdx.x * 32;
    const int b   = P0 >> 10;
    const int tc0 = P0 & 1023;

#pragma unroll 8
    for (int i = tid; i < 128 * 32; i += 256) {
        int c = i >> 5, p = i & 31;
        actA[c * 36 + p] = cein[(b * 128 + c) * 1024 + tc0 + p];
    }

    const float* Wl[3]  = {W0, W1, W2};
    const float* Bl[3]  = {B0, B1, B2};
    const float* Gl[3]  = {G0, G1, G2};
    const float* Bel[3] = {Be0, Be1, Be2};

    float* ain  = actA;
    float* aout = actB;

    const int o     = tid & 127;
    const int half  = tid >> 7;
    const int pbase = half * 16;
    const int wrp   = tid >> 5;
    const int lane  = tid & 31;

    for (int layer = 0; layer < 3; layer++) {
        __syncthreads();
        const float* W = Wl[layer];
#pragma unroll 8
        for (int i = tid; i < 128 * 32; i += 256) {
            int oo = i >> 5, c4 = (i & 31) << 2;
            float4 w = *(const float4*)(W + oo * 128 + c4);
            wbuf[(c4 + 0) * 129 + oo] = w.x;
            wbuf[(c4 + 1) * 129 + oo] = w.y;
            wbuf[(c4 + 2) * 129 + oo] = w.z;
            wbuf[(c4 + 3) * 129 + oo] = w.w;
        }
        if (tid < 128) {
            biasS[tid] = Bl[layer][tid];
            lngS[tid]  = Gl[layer][tid];
            lnbS[tid]  = Bel[layer][tid];
        }
        __syncthreads();

        float acc[16];
        float bo = biasS[o];
#pragma unroll
        for (int p = 0; p < 16; p++) acc[p] = bo;

        const float* arow = ain + pbase;
#pragma unroll 4
        for (int c = 0; c < 128; c++) {
            float w = wbuf[c * 129 + o];
            const float4* hr = (const float4*)(arow + c * 36);
            float4 h0 = hr[0], h1 = hr[1], h2 = hr[2], h3 = hr[3];
            acc[0]  = fmaf(w, h0.x, acc[0]);  acc[1]  = fmaf(w, h0.y, acc[1]);
            acc[2]  = fmaf(w, h0.z, acc[2]);  acc[3]  = fmaf(w, h0.w, acc[3]);
            acc[4]  = fmaf(w, h1.x, acc[4]);  acc[5]  = fmaf(w, h1.y, acc[5]);
            acc[6]  = fmaf(w, h1.z, acc[6]);  acc[7]  = fmaf(w, h1.w, acc[7]);
            acc[8]  = fmaf(w, h2.x, acc[8]);  acc[9]  = fmaf(w, h2.y, acc[9]);
            acc[10] = fmaf(w, h2.z, acc[10]); acc[11] = fmaf(w, h2.w, acc[11]);
            acc[12] = fmaf(w, h3.x, acc[12]); acc[13] = fmaf(w, h3.y, acc[13]);
            acc[14] = fmaf(w, h3.z, acc[14]); acc[15] = fmaf(w, h3.w, acc[15]);
        }

        float4* orow = (float4*)(aout + o * 36 + pbase);
        orow[0] = make_float4(acc[0],  acc[1],  acc[2],  acc[3]);
        orow[1] = make_float4(acc[4],  acc[5],  acc[6],  acc[7]);
        orow[2] = make_float4(acc[8],  acc[9],  acc[10], acc[11]);
        orow[3] = make_float4(acc[12], acc[13], acc[14], acc[15]);
        __syncthreads();

#pragma unroll
        for (int pp = 0; pp < 4; pp++) {
            int p = wrp * 4 + pp;
            float s = 0.f, s2 = 0.f;
#pragma unroll
            for (int k = 0; k < 4; k++) {
                float v = aout[(lane + k * 32) * 36 + p];
                s += v; s2 = fmaf(v, v, s2);
            }
#pragma unroll
            for (int off = 16; off > 0; off >>= 1) {
                s  += __shfl_xor_sync(0xffffffffu, s,  off);
                s2 += __shfl_xor_sync(0xffffffffu, s2, off);
            }
            if (lane == 0) {
                float mu  = s * (1.f / 128.f);
                float var = fmaf(s2, 1.f / 128.f, -mu * mu);
                statS[2 * p]     = mu;
                statS[2 * p + 1] = rsqrtf(var + 1e-5f);
            }
        }
        __syncthreads();

        float g = lngS[o], bb = lnbS[o];
#pragma unroll
        for (int p = 0; p < 16; p++) {
            float mu = statS[2 * (pbase + p)];
            float rs = statS[2 * (pbase + p) + 1];
            float v  = fmaf((acc[p] - mu) * rs, g, bb);
            acc[p] = fmaxf(v, 0.01f * v);
        }
        orow[0] = make_float4(acc[0],  acc[1],  acc[2],  acc[3]);
        orow[1] = make_float4(acc[4],  acc[5],  acc[6],  acc[7]);
        orow[2] = make_float4(acc[8],  acc[9],  acc[10], acc[11]);
        orow[3] = make_float4(acc[12], acc[13], acc[14], acc[15]);

        float* tsw = ain; ain = aout; aout = tsw;
    }

    __syncthreads();
#pragma unroll 8
    for (int i = tid; i < 256 * 32; i += 256) {
        int oo = i >> 5, c4 = (i & 31) << 2;
        float4 w = *(const float4*)(W3 + oo * 128 + c4);
        wbuf[(c4 + 0) * 257 + oo] = w.x;
        wbuf[(c4 + 1) * 257 + oo] = w.y;
        wbuf[(c4 + 2) * 257 + oo] = w.z;
        wbuf[(c4 + 3) * 257 + oo] = w.w;
    }
    __syncthreads();
    {
        float acc[32];
        float bo = B3[tid];
#pragma unroll
        for (int p = 0; p < 32; p++) acc[p] = bo;
#pragma unroll 2
        for (int c = 0; c < 128; c++) {
            float w = wbuf[c * 257 + tid];
            const float4* hr = (const float4*)(ain + c * 36);
#pragma unroll
            for (int q = 0; q < 8; q++) {
                float4 h = hr[q];
                acc[q * 4 + 0] = fmaf(w, h.x, acc[q * 4 + 0]);
                acc[q * 4 + 1] = fmaf(w, h.y, acc[q * 4 + 1]);
                acc[q * 4 + 2] = fmaf(w, h.z, acc[q * 4 + 2]);
                acc[q * 4 + 3] = fmaf(w, h.w, acc[q * 4 + 3]);
            }
        }
        float4* dst = (float4*)(g_film + (b * 256 + tid) * 1024 + tc0);
#pragma unroll
        for (int q = 0; q < 8; q++)
            dst[q] = make_float4(acc[q * 4], acc[q * 4 + 1], acc[q * 4 + 2], acc[q * 4 + 3]);
    }
}

// ===========================================================================
// Kernel 2: FiLM interp + per-channel 1->16->16->1 sine MLP + mixer + x4 up.
// 2 blocks/SM x 512 threads. Warp owns 4 channels; lane owns one sample
// pair. Layer 1 packs over OUTPUT pairs, outer-product over j with a
// one-iteration arg lookahead to hide MUFU latency. Scalar layer-0 args
// (no upk2), coalesced sw1 staging, contiguous task chunks.
// ===========================================================================
__global__ __launch_bounds__(512, 2) void newt_kernel(
    const float* __restrict__ ex, const float* __restrict__ iscale,
    const float* __restrict__ w0g, const float* __restrict__ b0g,
    const float* __restrict__ w1g, const float* __restrict__ b1g,
    const float* __restrict__ w2g, const float* __restrict__ b2g,
    const float* __restrict__ mixwg, const float* __restrict__ mixbg,
    float* __restrict__ outp)
{
    extern __shared__ float sm2[];
    float* sw1   = sm2;                 // 16384: [c][j][o], o fastest
    float* sw0b0 = sm2 + 16384;         // 2048: per (c,j): {w0, b0}
    float* sb1   = sm2 + 18432;         // 1024 natural
    float* sw2   = sm2 + 19456;         // 1024 natural
    float* sb2   = sm2 + 20480;         // 64
    float* smx   = sm2 + 20544;         // 64
    float* sis   = sm2 + 20608;         // 64
    float* red   = sm2 + 20672;         // 1024 (float2 per lane slot)

    const int tid = threadIdx.x;

    // stage sw1: coalesced LDG (linear over w1g [c][o][j]) + transposed STS
    for (int i = tid; i < 16384; i += 512) {
        float w = w1g[i];
        int c = i >> 8, o = (i >> 4) & 15, j = i & 15;
        sw1[(c << 8) + (j << 4) + o] = w;
    }
    for (int i = tid; i < 1024; i += 512) {
        int c = i >> 4, j = i & 15;
        sw0b0[(c << 5) + (j << 1) + 0] = w0g[i];
        sw0b0[(c << 5) + (j << 1) + 1] = b0g[i];
        sb1[i] = b1g[i];
        sw2[i] = w2g[i];
    }
    if (tid < 64) {
        sb2[tid] = b2g[tid];
        smx[tid] = mixwg[tid];
        sis[tid] = iscale[tid];
    }
    __syncthreads();

    const int lane = tid & 31;
    const int wid  = tid >> 5;
    const int side = lane >> 4;
    const float f0 = (2 * lane) * 0.015625f + 0.0078125f + 0.5f - (float)side;
    const float f1 = f0 + 0.015625f;
    const ull ZZ = pk2(0.f, 0.f);

    const int tstart = (int)(((long long)blockIdx.x * 4096) / gridDim.x);
    const int tend   = (int)(((long long)(blockIdx.x + 1) * 4096) / gridDim.x);

    for (int task = tstart; task < tend; task++) {
        const int b  = task >> 10;
        const int tt = task & 1023;
        const int t0 = tt << 6;
        int iA = tt - 1 + side; if (iA < 0) iA = 0;
        int iB = tt + side;     if (iB > 1023) iB = 1023;

        float mix0 = 0.f, mix1 = 0.f;
#pragma unroll 1
        for (int k = 0; k < 4; k++) {
            const int c = (wid << 2) + k;
            const float* fr = g_film + b * 262144 + (c << 10);

            float ga = __ldg(fr + iA), gb = __ldg(fr + iB);
            float ba = __ldg(fr + 65536 + iA), bb = __ldg(fr + 65536 + iB);
            float2 e2 = *(const float2*)(ex + (((b << 6) + c) << 16) + t0 + 2 * lane);
            float is = sis[c];

            float gd = gb - ga, bd = bb - ba;
            float x0 = is * fmaf(fmaf(f0, gd, ga), e2.x, fmaf(f0, bd, ba));
            float x1 = is * fmaf(fmaf(f1, gd, ga), e2.y, fmaf(f1, bd, ba));

            // init accumulators from b1 pairs: acc[2p+s] (o-pair p, sample s)
            ull acc[16];
            {
                const ull* b1p = (const ull*)(sb1 + (c << 4));
#pragma unroll
                for (int p = 0; p < 8; p++) { acc[2 * p] = b1p[p]; acc[2 * p + 1] = b1p[p]; }
            }

            // layer 0 + layer 1 fused, outer-product over j, arg lookahead
            const float2* wb  = (const float2*)(sw0b0 + (c << 5));
            const float*  w1c = sw1 + (c << 8);
            float2 wbc = wb[0];
            float a0 = fmaf(x0, wbc.x, wbc.y);
            float a1 = fmaf(x1, wbc.x, wbc.y);
#pragma unroll
            for (int j = 0; j < 16; j++) {
                float s0 = sin_cw(a0);
                float s1 = sin_cw(a1);
                if (j < 15) {
                    float2 wbn = wb[j + 1];
                    a0 = fmaf(x0, wbn.x, wbn.y);
                    a1 = fmaf(x1, wbn.x, wbn.y);
                }
                ull hh0 = pk2(s0, s0);
                ull hh1 = pk2(s1, s1);
                const ulonglong2* wr = (const ulonglong2*)(w1c + (j << 4));
#pragma unroll
                for (int q = 0; q < 4; q++) {
                    ulonglong2 wv = wr[q];
                    acc[4 * q + 0] = ffma2(hh0, wv.x, acc[4 * q + 0]);
                    acc[4 * q + 1] = ffma2(hh1, wv.x, acc[4 * q + 1]);
                    acc[4 * q + 2] = ffma2(hh0, wv.y, acc[4 * q + 2]);
                    acc[4 * q + 3] = ffma2(hh1, wv.y, acc[4 * q + 3]);
                }
            }

            // layer 2: sin(acc) dot w2 (packed over o-pairs)
            const ull* w2p = (const ull*)(sw2 + (c << 4));
            ull y0a = ZZ, y1a = ZZ;
#pragma unroll
            for (int p = 0; p < 8; p++) {
                float u0, u1, v0, v1;
                upk2(u0, u1, acc[2 * p]);
                upk2(v0, v1, acc[2 * p + 1]);
                ull wp = w2p[p];
                y0a = ffma2(pk2(__sinf(u0), __sinf(u1)), wp, y0a);
                y1a = ffma2(pk2(__sinf(v0), __sinf(v1)), wp, y1a);
            }
            float b2c = sb2[c];
            float y0l, y0h, y1l, y1h;
            upk2(y0l, y0h, y0a); upk2(y1l, y1h, y1a);
            float sy0 = __sinf(y0l + y0h + b2c);
            float sy1 = __sinf(y1l + y1h + b2c);

            // deferred gamma_n / beta_n + final FiLM + mix (scalar)
            float na = __ldg(fr + 131072 + iA), nb = __ldg(fr + 131072 + iB);
            float pa = __ldg(fr + 196608 + iA), pb = __ldg(fr + 196608 + iB);
            float nd = nb - na, pd = pb - pa;
            float m = smx[c];
            mix0 = fmaf(m, fmaf(fmaf(f0, nd, na), sy0, fmaf(f0, pd, pa)), mix0);
            mix1 = fmaf(m, fmaf(fmaf(f1, nd, na), sy1, fmaf(f1, pd, pa)), mix1);
        }

        *(float2*)(red + ((wid << 5) + lane) * 2) = make_float2(mix0, mix1);
        __syncthreads();
        if (tid < 64) {
            float s = __ldg(mixbg);
#pragma unroll
            for (int w = 0; w < 16; w++) s += red[(w << 6) + tid];
            *(float4*)(outp + (b << 18) + ((t0 + tid) << 2)) = make_float4(s, s, s, s);
        }
        __syncthreads();
    }
}

// ===========================================================================
extern "C" void kernel_launch(void* const* d_in, const int* in_sizes, int n_in,
                              void* d_out, int out_size) {
    const float* ex    = (const float*)d_in[0];
    const float* ce    = (const float*)d_in[1];
    const float* w0    = (const float*)d_in[2];
    const float* b0    = (const float*)d_in[3];
    const float* g0    = (const float*)d_in[4];
    const float* be0   = (const float*)d_in[5];
    const float* w1    = (const float*)d_in[6];
    const float* b1    = (const float*)d_in[7];
    const float* g1    = (const float*)d_in[8];
    const float* be1   = (const float*)d_in[9];
    const float* w2    = (const float*)d_in[10];
    const float* b2    = (const float*)d_in[11];
    const float* g2    = (const float*)d_in[12];
    const float* be2   = (const float*)d_in[13];
    const float* w3    = (const float*)d_in[14];
    const float* b3    = (const float*)d_in[15];
    const float* iscl  = (const float*)d_in[16];
    const float* sfw0  = (const float*)d_in[17];
    const float* sfb0  = (const float*)d_in[18];
    const float* sfw1  = (const float*)d_in[19];
    const float* sfb1  = (const float*)d_in[20];
    const float* sfw2  = (const float*)d_in[21];
    const float* sfb2  = (const float*)d_in[22];
    const float* mixw  = (const float*)d_in[23];
    const float* mixb  = (const float*)d_in[24];
    float* out = (float*)d_out;

    const int SM1 = 42688 * 4;   // 170752 B
    const int SM2 = 21696 * 4;   // 86784 B -> 2 blocks/SM
    cudaFuncSetAttribute(mlp_kernel,  cudaFuncAttributeMaxDynamicSharedMemorySize, SM1);
    cudaFuncSetAttribute(newt_kernel, cudaFuncAttributeMaxDynamicSharedMemorySize, SM2);

    int nsm = 148;
    cudaDeviceGetAttribute(&nsm, cudaDevAttrMultiProcessorCount, 0);
    if (nsm <= 0) nsm = 148;

    mlp_kernel<<<128, 256, SM1>>>(ce, w0, b0, g0, be0, w1, b1, g1, be1,
                                  w2, b2, g2, be2, w3, b3);
    newt_kernel<<<2 * nsm, 512, SM2>>>(ex, iscl, sfw0, sfb0, sfw1, sfb1,
                                       sfw2, sfb2, mixw, mixb, out);
}

// round 12
// speedup vs baseline: 1.2044x; 1.1358x over previous
#include <cuda_runtime.h>

typedef unsigned long long ull;

// film buffer: [b(4)][ch(256)][tc(1024)]
__device__ float g_film[4 * 256 * 1024];

// ---------------- packed f32x2 helpers (sm_103a FFMA2 path) ----------------
__device__ __forceinline__ ull pk2(float lo, float hi) {
    ull r; asm("mov.b64 %0, {%1, %2};" : "=l"(r) : "f"(lo), "f"(hi)); return r;
}
__device__ __forceinline__ void upk2(float& lo, float& hi, ull v) {
    asm("mov.b64 {%0, %1}, %2;" : "=f"(lo), "=f"(hi) : "l"(v));
}
__device__ __forceinline__ ull ffma2(ull a, ull b, ull c) {
    ull d; asm("fma.rn.f32x2 %0, %1, %2, %3;" : "=l"(d) : "l"(a), "l"(b), "l"(c)); return d;
}

// ===========================================================================
// Kernel 1: control-rate MLP. 128 blocks x 512 threads, 32 positions/block.
// o = tid&127, position-quarter = tid>>7 (8 positions per thread).
// ===========================================================================
__global__ __launch_bounds__(512) void mlp_kernel(
    const float* __restrict__ cein,
    const float* __restrict__ W0, const float* __restrict__ B0,
    const float* __restrict__ G0, const float* __restrict__ Be0,
    const float* __restrict__ W1, const float* __restrict__ B1,
    const float* __restrict__ G1, const float* __restrict__ Be1,
    const float* __restrict__ W2, const float* __restrict__ B2,
    const float* __restrict__ G2, const float* __restrict__ Be2,
    const float* __restrict__ W3, const float* __restrict__ B3)
{
    extern __shared__ float sm1[];
    float* wbuf  = sm1;              // up to 128*257 = 32896 floats
    float* actA  = sm1 + 32896;      // 128 rows x pitch 36
    float* actB  = actA + 4608;
    float* biasS = actB + 4608;      // 256
    float* lngS  = biasS + 256;      // 128
    float* lnbS  = lngS + 128;       // 128
    float* statS = lnbS + 128;       // 64

    const int tid = threadIdx.x;
    const int P0  = blockIdx.x * 32;
    const int b   = P0 >> 10;
    const int tc0 = P0 & 1023;

#pragma unroll 4
    for (int i = tid; i < 128 * 32; i += 512) {
        int c = i >> 5, p = i & 31;
        actA[c * 36 + p] = cein[(b * 128 + c) * 1024 + tc0 + p];
    }

    const float* Wl[3]  = {W0, W1, W2};
    const float* Bl[3]  = {B0, B1, B2};
    const float* Gl[3]  = {G0, G1, G2};
    const float* Bel[3] = {Be0, Be1, Be2};

    float* ain  = actA;
    float* aout = actB;

    const int o     = tid & 127;
    const int q4    = tid >> 7;          // 0..3
    const int pbase = q4 * 8;
    const int wrp   = tid >> 5;          // 0..15
    const int lane  = tid & 31;

    for (int layer = 0; layer < 3; layer++) {
        __syncthreads();
        const float* W = Wl[layer];
#pragma unroll 4
        for (int i = tid; i < 128 * 32; i += 512) {
            int oo = i >> 5, c4 = (i & 31) << 2;
            float4 w = *(const float4*)(W + oo * 128 + c4);
            wbuf[(c4 + 0) * 129 + oo] = w.x;
            wbuf[(c4 + 1) * 129 + oo] = w.y;
            wbuf[(c4 + 2) * 129 + oo] = w.z;
            wbuf[(c4 + 3) * 129 + oo] = w.w;
        }
        if (tid < 128) {
            biasS[tid] = Bl[layer][tid];
            lngS[tid]  = Gl[layer][tid];
            lnbS[tid]  = Bel[layer][tid];
        }
        __syncthreads();

        float acc[8];
        float bo = biasS[o];
#pragma unroll
        for (int p = 0; p < 8; p++) acc[p] = bo;

        const float* arow = ain + pbase;
#pragma unroll 4
        for (int c = 0; c < 128; c++) {
            float w = wbuf[c * 129 + o];
            const float4* hr = (const float4*)(arow + c * 36);
            float4 h0 = hr[0], h1 = hr[1];
            acc[0] = fmaf(w, h0.x, acc[0]); acc[1] = fmaf(w, h0.y, acc[1]);
            acc[2] = fmaf(w, h0.z, acc[2]); acc[3] = fmaf(w, h0.w, acc[3]);
            acc[4] = fmaf(w, h1.x, acc[4]); acc[5] = fmaf(w, h1.y, acc[5]);
            acc[6] = fmaf(w, h1.z, acc[6]); acc[7] = fmaf(w, h1.w, acc[7]);
        }

        float4* orow = (float4*)(aout + o * 36 + pbase);
        orow[0] = make_float4(acc[0], acc[1], acc[2], acc[3]);
        orow[1] = make_float4(acc[4], acc[5], acc[6], acc[7]);
        __syncthreads();

#pragma unroll
        for (int pp = 0; pp < 2; pp++) {
            int p = wrp * 2 + pp;
            float s = 0.f, s2 = 0.f;
#pragma unroll
            for (int k = 0; k < 4; k++) {
                float v = aout[(lane + k * 32) * 36 + p];
                s += v; s2 = fmaf(v, v, s2);
            }
#pragma unroll
            for (int off = 16; off > 0; off >>= 1) {
                s  += __shfl_xor_sync(0xffffffffu, s,  off);
                s2 += __shfl_xor_sync(0xffffffffu, s2, off);
            }
            if (lane == 0) {
                float mu  = s * (1.f / 128.f);
                float var = fmaf(s2, 1.f / 128.f, -mu * mu);
                statS[2 * p]     = mu;
                statS[2 * p + 1] = rsqrtf(var + 1e-5f);
            }
        }
        __syncthreads();

        float g = lngS[o], bb = lnbS[o];
#pragma unroll
        for (int p = 0; p < 8; p++) {
            float mu = statS[2 * (pbase + p)];
            float rs = statS[2 * (pbase + p) + 1];
            float v  = fmaf((acc[p] - mu) * rs, g, bb);
            acc[p] = fmaxf(v, 0.01f * v);
        }
        orow[0] = make_float4(acc[0], acc[1], acc[2], acc[3]);
        orow[1] = make_float4(acc[4], acc[5], acc[6], acc[7]);

        float* tsw = ain; ain = aout; aout = tsw;
    }

    __syncthreads();
#pragma unroll 4
    for (int i = tid; i < 256 * 32; i += 512) {
        int oo = i >> 5, c4 = (i & 31) << 2;
        float4 w = *(const float4*)(W3 + oo * 128 + c4);
        wbuf[(c4 + 0) * 257 + oo] = w.x;
        wbuf[(c4 + 1) * 257 + oo] = w.y;
        wbuf[(c4 + 2) * 257 + oo] = w.z;
        wbuf[(c4 + 3) * 257 + oo] = w.w;
    }
    __syncthreads();
    {
        const int oo  = tid & 255;
        const int h2  = tid >> 8;        // 0..1
        const int pb2 = h2 * 16;
        float acc[16];
        float bo = B3[oo];
#pragma unroll
        for (int p = 0; p < 16; p++) acc[p] = bo;
#pragma unroll 2
        for (int c = 0; c < 128; c++) {
            float w = wbuf[c * 257 + oo];
            const float4* hr = (const float4*)(ain + c * 36 + pb2);
#pragma unroll
            for (int q = 0; q < 4; q++) {
                float4 h = hr[q];
                acc[q * 4 + 0] = fmaf(w, h.x, acc[q * 4 + 0]);
                acc[q * 4 + 1] = fmaf(w, h.y, acc[q * 4 + 1]);
                acc[q * 4 + 2] = fmaf(w, h.z, acc[q * 4 + 2]);
                acc[q * 4 + 3] = fmaf(w, h.w, acc[q * 4 + 3]);
            }
        }
        float4* dst = (float4*)(g_film + (b * 256 + oo) * 1024 + tc0 + pb2);
#pragma unroll
        for (int q = 0; q < 4; q++)
            dst[q] = make_float4(acc[q * 4], acc[q * 4 + 1], acc[q * 4 + 2], acc[q * 4 + 3]);
    }
}

// ===========================================================================
// Kernel 2: FiLM interp + per-channel 1->16->16->1 sine MLP + mixer + x4 up.
// 2 blocks/SM x 512 threads. Layer-0 sins now use raw MUFU.SIN (no CW
// reduction): -48 fma per channel-sample (-22% fma-pipe work).
// ===========================================================================
__global__ __launch_bounds__(512, 2) void newt_kernel(
    const float* __restrict__ ex, const float* __restrict__ iscale,
    const float* __restrict__ w0g, const float* __restrict__ b0g,
    const float* __restrict__ w1g, const float* __restrict__ b1g,
    const float* __restrict__ w2g, const float* __restrict__ b2g,
    const float* __restrict__ mixwg, const float* __restrict__ mixbg,
    float* __restrict__ outp)
{
    extern __shared__ float sm2[];
    float* sw1   = sm2;                 // 16384: [c][j][o], o fastest
    float* sw0b0 = sm2 + 16384;         // 2048: per (c,j): {w0, b0}
    float* sb1   = sm2 + 18432;         // 1024 natural
    float* sw2   = sm2 + 19456;         // 1024 natural
    float* sb2   = sm2 + 20480;         // 64
    float* smx   = sm2 + 20544;         // 64
    float* sis   = sm2 + 20608;         // 64
    float* red   = sm2 + 20672;         // 1024 (float2 per lane slot)

    const int tid = threadIdx.x;

    // stage sw1: coalesced LDG (linear over w1g [c][o][j]) + transposed STS
    for (int i = tid; i < 16384; i += 512) {
        float w = w1g[i];
        int c = i >> 8, o = (i >> 4) & 15, j = i & 15;
        sw1[(c << 8) + (j << 4) + o] = w;
    }
    for (int i = tid; i < 1024; i += 512) {
        int c = i >> 4, j = i & 15;
        sw0b0[(c << 5) + (j << 1) + 0] = w0g[i];
        sw0b0[(c << 5) + (j << 1) + 1] = b0g[i];
        sb1[i] = b1g[i];
        sw2[i] = w2g[i];
    }
    if (tid < 64) {
        sb2[tid] = b2g[tid];
        smx[tid] = mixwg[tid];
        sis[tid] = iscale[tid];
    }
    __syncthreads();

    const int lane = tid & 31;
    const int wid  = tid >> 5;
    const int side = lane >> 4;
    const float f0 = (2 * lane) * 0.015625f + 0.0078125f + 0.5f - (float)side;
    const float f1 = f0 + 0.015625f;
    const ull ZZ = pk2(0.f, 0.f);

    const int tstart = (int)(((long long)blockIdx.x * 4096) / gridDim.x);
    const int tend   = (int)(((long long)(blockIdx.x + 1) * 4096) / gridDim.x);

    for (int task = tstart; task < tend; task++) {
        const int b  = task >> 10;
        const int tt = task & 1023;
        const int t0 = tt << 6;
        int iA = tt - 1 + side; if (iA < 0) iA = 0;
        int iB = tt + side;     if (iB > 1023) iB = 1023;

        float mix0 = 0.f, mix1 = 0.f;
#pragma unroll 1
        for (int k = 0; k < 4; k++) {
            const int c = (wid << 2) + k;
            const float* fr = g_film + b * 262144 + (c << 10);

            float ga = __ldg(fr + iA), gb = __ldg(fr + iB);
            float ba = __ldg(fr + 65536 + iA), bb = __ldg(fr + 65536 + iB);
            float2 e2 = *(const float2*)(ex + (((b << 6) + c) << 16) + t0 + 2 * lane);
            float is = sis[c];

            float gd = gb - ga, bd = bb - ba;
            float x0 = is * fmaf(fmaf(f0, gd, ga), e2.x, fmaf(f0, bd, ba));
            float x1 = is * fmaf(fmaf(f1, gd, ga), e2.y, fmaf(f1, bd, ba));

            // init accumulators from b1 pairs: acc[2p+s] (o-pair p, sample s)
            ull acc[16];
            {
                const ull* b1p = (const ull*)(sb1 + (c << 4));
#pragma unroll
                for (int p = 0; p < 8; p++) { acc[2 * p] = b1p[p]; acc[2 * p + 1] = b1p[p]; }
            }

            // layer 0 + layer 1 fused, outer-product over j, arg lookahead
            const float2* wb  = (const float2*)(sw0b0 + (c << 5));
            const float*  w1c = sw1 + (c << 8);
            float2 wbc = wb[0];
            float a0 = fmaf(x0, wbc.x, wbc.y);
            float a1 = fmaf(x1, wbc.x, wbc.y);
#pragma unroll
            for (int j = 0; j < 16; j++) {
                float s0 = __sinf(a0);
                float s1 = __sinf(a1);
                if (j < 15) {
                    float2 wbn = wb[j + 1];
                    a0 = fmaf(x0, wbn.x, wbn.y);
                    a1 = fmaf(x1, wbn.x, wbn.y);
                }
                ull hh0 = pk2(s0, s0);
                ull hh1 = pk2(s1, s1);
                const ulonglong2* wr = (const ulonglong2*)(w1c + (j << 4));
#pragma unroll
                for (int q = 0; q < 4; q++) {
                    ulonglong2 wv = wr[q];
                    acc[4 * q + 0] = ffma2(hh0, wv.x, acc[4 * q + 0]);
                    acc[4 * q + 1] = ffma2(hh1, wv.x, acc[4 * q + 1]);
                    acc[4 * q + 2] = ffma2(hh0, wv.y, acc[4 * q + 2]);
                    acc[4 * q + 3] = ffma2(hh1, wv.y, acc[4 * q + 3]);
                }
            }

            // layer 2: sin(acc) dot w2 (packed over o-pairs)
            const ull* w2p = (const ull*)(sw2 + (c << 4));
            ull y0a = ZZ, y1a = ZZ;
#pragma unroll
            for (int p = 0; p < 8; p++) {
                float u0, u1, v0, v1;
                upk2(u0, u1, acc[2 * p]);
                upk2(v0, v1, acc[2 * p + 1]);
                ull wp = w2p[p];
                y0a = ffma2(pk2(__sinf(u0), __sinf(u1)), wp, y0a);
                y1a = ffma2(pk2(__sinf(v0), __sinf(v1)), wp, y1a);
            }
            float b2c = sb2[c];
            float y0l, y0h, y1l, y1h;
            upk2(y0l, y0h, y0a); upk2(y1l, y1h, y1a);
            float sy0 = __sinf(y0l + y0h + b2c);
            float sy1 = __sinf(y1l + y1h + b2c);

            // deferred gamma_n / beta_n + final FiLM + mix (scalar)
            float na = __ldg(fr + 131072 + iA), nb = __ldg(fr + 131072 + iB);
            float pa = __ldg(fr + 196608 + iA), pb = __ldg(fr + 196608 + iB);
            float nd = nb - na, pd = pb - pa;
            float m = smx[c];
            mix0 = fmaf(m, fmaf(fmaf(f0, nd, na), sy0, fmaf(f0, pd, pa)), mix0);
            mix1 = fmaf(m, fmaf(fmaf(f1, nd, na), sy1, fmaf(f1, pd, pa)), mix1);
        }

        *(float2*)(red + ((wid << 5) + lane) * 2) = make_float2(mix0, mix1);
        __syncthreads();
        if (tid < 64) {
            float s = __ldg(mixbg);
#pragma unroll
            for (int w = 0; w < 16; w++) s += red[(w << 6) + tid];
            *(float4*)(outp + (b << 18) + ((t0 + tid) << 2)) = make_float4(s, s, s, s);
        }
        __syncthreads();
    }
}

// ===========================================================================
extern "C" void kernel_launch(void* const* d_in, const int* in_sizes, int n_in,
                              void* d_out, int out_size) {
    const float* ex    = (const float*)d_in[0];
    const float* ce    = (const float*)d_in[1];
    const float* w0    = (const float*)d_in[2];
    const float* b0    = (const float*)d_in[3];
    const float* g0    = (const float*)d_in[4];
    const float* be0   = (const float*)d_in[5];
    const float* w1    = (const float*)d_in[6];
    const float* b1    = (const float*)d_in[7];
    const float* g1    = (const float*)d_in[8];
    const float* be1   = (const float*)d_in[9];
    const float* w2    = (const float*)d_in[10];
    const float* b2    = (const float*)d_in[11];
    const float* g2    = (const float*)d_in[12];
    const float* be2   = (const float*)d_in[13];
    const float* w3    = (const float*)d_in[14];
    const float* b3    = (const float*)d_in[15];
    const float* iscl  = (const float*)d_in[16];
    const float* sfw0  = (const float*)d_in[17];
    const float* sfb0  = (const float*)d_in[18];
    const float* sfw1  = (const float*)d_in[19];
    const float* sfb1  = (const float*)d_in[20];
    const float* sfw2  = (const float*)d_in[21];
    const float* sfb2  = (const float*)d_in[22];
    const float* mixw  = (const float*)d_in[23];
    const float* mixb  = (const float*)d_in[24];
    float* out = (float*)d_out;

    const int SM1 = 42688 * 4;   // 170752 B
    const int SM2 = 21696 * 4;   // 86784 B -> 2 blocks/SM
    cudaFuncSetAttribute(mlp_kernel,  cudaFuncAttributeMaxDynamicSharedMemorySize, SM1);
    cudaFuncSetAttribute(newt_kernel, cudaFuncAttributeMaxDynamicSharedMemorySize, SM2);

    int nsm = 148;
    cudaDeviceGetAttribute(&nsm, cudaDevAttrMultiProcessorCount, 0);
    if (nsm <= 0) nsm = 148;

    mlp_kernel<<<128, 512, SM1>>>(ce, w0, b0, g0, be0, w1, b1, g1, be1,
                                  w2, b2, g2, be2, w3, b3);
    newt_kernel<<<2 * nsm, 512, SM2>>>(ex, iscl, sfw0, sfb0, sfw1, sfb1,
                                       sfw2, sfb2, mixw, mixb, out);
}